// round 3
// baseline (speedup 1.0000x reference)
#include <cuda_runtime.h>

// inverse lifting wavelet: (16,256,128,128) f32 -> (16,64,256,256) f32
//
// Y1[b,c,g,h,w]  = in[b, g*64+c, h, w]
// s_g(h,w)       = M2[g,:] . Y1[b,c,:,h,w]
// Y3_i(h,w)      = M1[i,0]*s0(h,w) + M1[i,1]*s1(h-1,w)
//                + M1[i,2]*s2(h,w-1) + M1[i,3]*s3(h-1,w-1)   (indices wrap)
// out[b,c,2h+p,2w+q] = Y3_{2p+q}(h,w)
//
// Decomposition: 4096 warps total (16 b x 64 c x 4 h-tiles of 32 rows),
// launched as 1024 blocks x 128 threads -> ALL warps resident in ONE wave
// (148 SMs x 8 blocks x 4 warps = 4736 slots >= 4096). Zero wave-quantization
// tail; each warp does exactly one strip.

#define FULL 0xffffffffu

__device__ __forceinline__ float4 ldcs4(const float* p) {
    return __ldcs((const float4*)p);
}
__device__ __forceinline__ void stcs4(float* p, float4 v) {
    __stcs((float4*)p, v);
}

__global__ __launch_bounds__(128, 8)
void inlwt_kernel(const float* __restrict__ in, float* __restrict__ out) {
    constexpr int H1 = 128, W1 = 128, C = 64;
    constexpr int HT = 32;                 // rows per warp strip
    // 4 h-tiles per (b,c) plane

    const int gw   = (blockIdx.x * blockDim.x + threadIdx.x) >> 5;  // 0..4095
    const int lane = threadIdx.x & 31;

    const int htile = gw & 3;
    const int cc    = (gw >> 2) & 63;
    const int b     = gw >> 8;

    const int h0 = htile * HT;
    const int w0 = lane * 4;

    const float* inb  = in  + (size_t)(b * 256 + cc) * (H1 * W1);
    float*       outb = out + (size_t)(b * C   + cc) * (size_t)(2 * H1) * (2 * W1);
    const size_t gs   = (size_t)64 * H1 * W1;   // channel-group stride

    // ---- load previous row (wraps at h==0) ----
    const int hp = (h0 == 0) ? (H1 - 1) : (h0 - 1);
    float4 pv0 = ldcs4(inb + 0 * gs + (size_t)hp * W1 + w0);
    float4 pv1 = ldcs4(inb + 1 * gs + (size_t)hp * W1 + w0);
    float4 pv2 = ldcs4(inb + 2 * gs + (size_t)hp * W1 + w0);
    float4 pv3 = ldcs4(inb + 3 * gs + (size_t)hp * W1 + w0);

    #pragma unroll 4
    for (int h = h0; h < h0 + HT; ++h) {
        float4 cv0 = ldcs4(inb + 0 * gs + (size_t)h * W1 + w0);
        float4 cv1 = ldcs4(inb + 1 * gs + (size_t)h * W1 + w0);
        float4 cv2 = ldcs4(inb + 2 * gs + (size_t)h * W1 + w0);
        float4 cv3 = ldcs4(inb + 3 * gs + (size_t)h * W1 + w0);

        float cg0[4] = {cv0.x, cv0.y, cv0.z, cv0.w};
        float cg1[4] = {cv1.x, cv1.y, cv1.z, cv1.w};
        float cg2[4] = {cv2.x, cv2.y, cv2.z, cv2.w};
        float cg3[4] = {cv3.x, cv3.y, cv3.z, cv3.w};
        float pg0[4] = {pv0.x, pv0.y, pv0.z, pv0.w};
        float pg1[4] = {pv1.x, pv1.y, pv1.z, pv1.w};
        float pg2[4] = {pv2.x, pv2.y, pv2.z, pv2.w};
        float pg3[4] = {pv3.x, pv3.y, pv3.z, pv3.w};

        float s0[4], s1[4], s2[4], s3[4];
        #pragma unroll
        for (int i = 0; i < 4; ++i) {
            // M2 rows 0,2 applied to current row; rows 1,3 to previous row
            s0[i] =  1.3968f * cg0[i] - 0.2212f * cg1[i] - 0.5412f * cg2[i] + 1.3066f * cg3[i];
            s2[i] = -0.2212f * cg0[i] - 1.3968f * cg1[i] - 1.3066f * cg2[i] - 0.5412f * cg3[i];
            s1[i] =  0.2212f * pg0[i] + 1.3968f * pg1[i] - 1.3066f * pg2[i] - 0.5412f * pg3[i];
            s3[i] = -1.3968f * pg0[i] + 0.2212f * pg1[i] - 0.5412f * pg2[i] + 1.3066f * pg3[i];
        }

        // w-1 values: circular shift across the warp (implements roll wrap at w=0)
        const int src = (lane + 31) & 31;
        float s2n = __shfl_sync(FULL, s2[3], src);
        float s3n = __shfl_sync(FULL, s3[3], src);
        float a2[4] = {s2n, s2[0], s2[1], s2[2]};
        float a3[4] = {s3n, s3[0], s3[1], s3[2]};

        float o0[4], o1[4], o2[4], o3[4];
        #pragma unroll
        for (int i = 0; i < 4; ++i) {
            // M1 stage: Y3_i = M1[i,:] . (s0, s1, a2, a3)
            o0[i] =  0.2166f * s0[i] - 0.0256f * s1[i] + 0.1213f * a2[i] + 0.0144f * a3[i];
            o1[i] =  0.0256f * s0[i] + 0.2166f * s1[i] + 0.0144f * a2[i] - 0.1213f * a3[i];
            o2[i] =  0.1213f * s0[i] - 0.0144f * s1[i] - 0.2166f * a2[i] - 0.0256f * a3[i];
            o3[i] = -0.0144f * s0[i] - 0.1213f * s1[i] + 0.0256f * a2[i] - 0.2166f * a3[i];
        }

        // out rows 2h (Y3_0,Y3_1 interleaved) and 2h+1 (Y3_2,Y3_3)
        float* rtop = outb + (size_t)(2 * h)     * 256 + 8 * lane;
        float* rbot = outb + (size_t)(2 * h + 1) * 256 + 8 * lane;
        stcs4(rtop,     make_float4(o0[0], o1[0], o0[1], o1[1]));
        stcs4(rtop + 4, make_float4(o0[2], o1[2], o0[3], o1[3]));
        stcs4(rbot,     make_float4(o2[0], o3[0], o2[1], o3[1]));
        stcs4(rbot + 4, make_float4(o2[2], o3[2], o2[3], o3[3]));

        pv0 = cv0; pv1 = cv1; pv2 = cv2; pv3 = cv3;
    }
}

extern "C" void kernel_launch(void* const* d_in, const int* in_sizes, int n_in,
                              void* d_out, int out_size) {
    const float* in = (const float*)d_in[0];
    float* out = (float*)d_out;
    // 16 b * 64 c * 4 htiles = 4096 warps; 4 warps per block -> 1024 blocks,
    // all resident in a single wave (zero tail).
    inlwt_kernel<<<1024, 128>>>(in, out);
}

// round 4
// speedup vs baseline: 1.2096x; 1.2096x over previous
#include <cuda_runtime.h>

// inverse lifting wavelet: (16,256,128,128) f32 -> (16,64,256,256) f32
//
// Y1[b,c,g,h,w]  = in[b, g*64+c, h, w]
// s_g(h,w)       = M2[g,:] . Y1[b,c,:,h,w]
// Y3_i(h,w)      = M1[i,0]*s0(h,w) + M1[i,1]*s1(h-1,w)
//                + M1[i,2]*s2(h,w-1) + M1[i,3]*s3(h-1,w-1)   (indices wrap)
// out[b,c,2h+p,2w+q] = Y3_{2p+q}(h,w)
//
// R4: many-small-blocks regime (R2 was best). HT=8 rows/strip -> 16384 warp
// strips in 4096 blocks of 128 threads: fine-grained block backfill shrinks
// the makespan tail. launch_bounds(128,10) caps regs at 51 -> 40 warps/SM
// residency (was 32) for more memory-level parallelism.

#define FULL 0xffffffffu

__device__ __forceinline__ float4 ldcs4(const float* p) {
    return __ldcs((const float4*)p);
}
__device__ __forceinline__ void stcs4(float* p, float4 v) {
    __stcs((float4*)p, v);
}

__global__ __launch_bounds__(128, 10)
void inlwt_kernel(const float* __restrict__ in, float* __restrict__ out) {
    constexpr int H1 = 128, W1 = 128, C = 64;
    constexpr int HT = 8;                  // rows per warp strip
    // 16 h-tiles per (b,c) plane

    const int gw   = (blockIdx.x * blockDim.x + threadIdx.x) >> 5;  // 0..16383
    const int lane = threadIdx.x & 31;

    const int htile = gw & 15;
    const int cc    = (gw >> 4) & 63;
    const int b     = gw >> 10;

    const int h0 = htile * HT;
    const int w0 = lane * 4;

    const float* inb  = in  + (size_t)(b * 256 + cc) * (H1 * W1);
    float*       outb = out + (size_t)(b * C   + cc) * (size_t)(2 * H1) * (2 * W1);
    const size_t gs   = (size_t)64 * H1 * W1;   // channel-group stride

    // ---- load previous row (wraps at h==0) ----
    const int hp = (h0 == 0) ? (H1 - 1) : (h0 - 1);
    float4 pv0 = ldcs4(inb + 0 * gs + (size_t)hp * W1 + w0);
    float4 pv1 = ldcs4(inb + 1 * gs + (size_t)hp * W1 + w0);
    float4 pv2 = ldcs4(inb + 2 * gs + (size_t)hp * W1 + w0);
    float4 pv3 = ldcs4(inb + 3 * gs + (size_t)hp * W1 + w0);

    #pragma unroll 4
    for (int h = h0; h < h0 + HT; ++h) {
        float4 cv0 = ldcs4(inb + 0 * gs + (size_t)h * W1 + w0);
        float4 cv1 = ldcs4(inb + 1 * gs + (size_t)h * W1 + w0);
        float4 cv2 = ldcs4(inb + 2 * gs + (size_t)h * W1 + w0);
        float4 cv3 = ldcs4(inb + 3 * gs + (size_t)h * W1 + w0);

        float cg0[4] = {cv0.x, cv0.y, cv0.z, cv0.w};
        float cg1[4] = {cv1.x, cv1.y, cv1.z, cv1.w};
        float cg2[4] = {cv2.x, cv2.y, cv2.z, cv2.w};
        float cg3[4] = {cv3.x, cv3.y, cv3.z, cv3.w};
        float pg0[4] = {pv0.x, pv0.y, pv0.z, pv0.w};
        float pg1[4] = {pv1.x, pv1.y, pv1.z, pv1.w};
        float pg2[4] = {pv2.x, pv2.y, pv2.z, pv2.w};
        float pg3[4] = {pv3.x, pv3.y, pv3.z, pv3.w};

        float s0[4], s1[4], s2[4], s3[4];
        #pragma unroll
        for (int i = 0; i < 4; ++i) {
            // M2 rows 0,2 applied to current row; rows 1,3 to previous row
            s0[i] =  1.3968f * cg0[i] - 0.2212f * cg1[i] - 0.5412f * cg2[i] + 1.3066f * cg3[i];
            s2[i] = -0.2212f * cg0[i] - 1.3968f * cg1[i] - 1.3066f * cg2[i] - 0.5412f * cg3[i];
            s1[i] =  0.2212f * pg0[i] + 1.3968f * pg1[i] - 1.3066f * pg2[i] - 0.5412f * pg3[i];
            s3[i] = -1.3968f * pg0[i] + 0.2212f * pg1[i] - 0.5412f * pg2[i] + 1.3066f * pg3[i];
        }

        // w-1 values: circular shift across the warp (implements roll wrap at w=0)
        const int src = (lane + 31) & 31;
        float s2n = __shfl_sync(FULL, s2[3], src);
        float s3n = __shfl_sync(FULL, s3[3], src);
        float a2[4] = {s2n, s2[0], s2[1], s2[2]};
        float a3[4] = {s3n, s3[0], s3[1], s3[2]};

        float o0[4], o1[4], o2[4], o3[4];
        #pragma unroll
        for (int i = 0; i < 4; ++i) {
            // M1 stage: Y3_i = M1[i,:] . (s0, s1, a2, a3)
            o0[i] =  0.2166f * s0[i] - 0.0256f * s1[i] + 0.1213f * a2[i] + 0.0144f * a3[i];
            o1[i] =  0.0256f * s0[i] + 0.2166f * s1[i] + 0.0144f * a2[i] - 0.1213f * a3[i];
            o2[i] =  0.1213f * s0[i] - 0.0144f * s1[i] - 0.2166f * a2[i] - 0.0256f * a3[i];
            o3[i] = -0.0144f * s0[i] - 0.1213f * s1[i] + 0.0256f * a2[i] - 0.2166f * a3[i];
        }

        // out rows 2h (Y3_0,Y3_1 interleaved) and 2h+1 (Y3_2,Y3_3)
        float* rtop = outb + (size_t)(2 * h)     * 256 + 8 * lane;
        float* rbot = outb + (size_t)(2 * h + 1) * 256 + 8 * lane;
        stcs4(rtop,     make_float4(o0[0], o1[0], o0[1], o1[1]));
        stcs4(rtop + 4, make_float4(o0[2], o1[2], o0[3], o1[3]));
        stcs4(rbot,     make_float4(o2[0], o3[0], o2[1], o3[1]));
        stcs4(rbot + 4, make_float4(o2[2], o3[2], o2[3], o3[3]));

        pv0 = cv0; pv1 = cv1; pv2 = cv2; pv3 = cv3;
    }
}

extern "C" void kernel_launch(void* const* d_in, const int* in_sizes, int n_in,
                              void* d_out, int out_size) {
    const float* in = (const float*)d_in[0];
    float* out = (float*)d_out;
    // 16 b * 64 c * 16 htiles = 16384 warps; 4 warps per block -> 4096 blocks.
    inlwt_kernel<<<4096, 128>>>(in, out);
}

// round 5
// speedup vs baseline: 1.2193x; 1.0080x over previous
#include <cuda_runtime.h>

// inverse lifting wavelet: (16,256,128,128) f32 -> (16,64,256,256) f32
//
// Y1[b,c,g,h,w]  = in[b, g*64+c, h, w]
// s_g(h,w)       = M2[g,:] . Y1[b,c,:,h,w]
// Y3_i(h,w)      = M1[i,0]*s0(h,w) + M1[i,1]*s1(h-1,w)
//                + M1[i,2]*s2(h,w-1) + M1[i,3]*s3(h-1,w-1)   (indices wrap)
// out[b,c,2h+p,2w+q] = Y3_{2p+q}(h,w)
//
// R5: HT=8 strips, 4096 blocks (fine-grain backfill, won R4) + explicit
// one-row prefetch software pipeline: 8 LDG.128 in flight per warp instead
// of 4. launch_bounds(128,8) -> 64-reg cap to fit the prefetch registers.

#define FULL 0xffffffffu

__device__ __forceinline__ float4 ldcs4(const float* p) {
    return __ldcs((const float4*)p);
}
__device__ __forceinline__ void stcs4(float* p, float4 v) {
    __stcs((float4*)p, v);
}

// Compute one output row-pair from prev-row regs (pv*) and cur-row regs (cv*).
__device__ __forceinline__ void compute_store(
    const float4& pv0, const float4& pv1, const float4& pv2, const float4& pv3,
    const float4& cv0, const float4& cv1, const float4& cv2, const float4& cv3,
    float* __restrict__ outb, int h, int lane)
{
    float cg0[4] = {cv0.x, cv0.y, cv0.z, cv0.w};
    float cg1[4] = {cv1.x, cv1.y, cv1.z, cv1.w};
    float cg2[4] = {cv2.x, cv2.y, cv2.z, cv2.w};
    float cg3[4] = {cv3.x, cv3.y, cv3.z, cv3.w};
    float pg0[4] = {pv0.x, pv0.y, pv0.z, pv0.w};
    float pg1[4] = {pv1.x, pv1.y, pv1.z, pv1.w};
    float pg2[4] = {pv2.x, pv2.y, pv2.z, pv2.w};
    float pg3[4] = {pv3.x, pv3.y, pv3.z, pv3.w};

    float s0[4], s1[4], s2[4], s3[4];
    #pragma unroll
    for (int i = 0; i < 4; ++i) {
        // M2 rows 0,2 applied to current row; rows 1,3 to previous row
        s0[i] =  1.3968f * cg0[i] - 0.2212f * cg1[i] - 0.5412f * cg2[i] + 1.3066f * cg3[i];
        s2[i] = -0.2212f * cg0[i] - 1.3968f * cg1[i] - 1.3066f * cg2[i] - 0.5412f * cg3[i];
        s1[i] =  0.2212f * pg0[i] + 1.3968f * pg1[i] - 1.3066f * pg2[i] - 0.5412f * pg3[i];
        s3[i] = -1.3968f * pg0[i] + 0.2212f * pg1[i] - 0.5412f * pg2[i] + 1.3066f * pg3[i];
    }

    // w-1 values: circular shift across the warp (implements roll wrap at w=0)
    const int src = (lane + 31) & 31;
    float s2n = __shfl_sync(FULL, s2[3], src);
    float s3n = __shfl_sync(FULL, s3[3], src);
    float a2[4] = {s2n, s2[0], s2[1], s2[2]};
    float a3[4] = {s3n, s3[0], s3[1], s3[2]};

    float o0[4], o1[4], o2[4], o3[4];
    #pragma unroll
    for (int i = 0; i < 4; ++i) {
        // M1 stage: Y3_i = M1[i,:] . (s0, s1, a2, a3)
        o0[i] =  0.2166f * s0[i] - 0.0256f * s1[i] + 0.1213f * a2[i] + 0.0144f * a3[i];
        o1[i] =  0.0256f * s0[i] + 0.2166f * s1[i] + 0.0144f * a2[i] - 0.1213f * a3[i];
        o2[i] =  0.1213f * s0[i] - 0.0144f * s1[i] - 0.2166f * a2[i] - 0.0256f * a3[i];
        o3[i] = -0.0144f * s0[i] - 0.1213f * s1[i] + 0.0256f * a2[i] - 0.2166f * a3[i];
    }

    // out rows 2h (Y3_0,Y3_1 interleaved) and 2h+1 (Y3_2,Y3_3)
    float* rtop = outb + (size_t)(2 * h)     * 256 + 8 * lane;
    float* rbot = outb + (size_t)(2 * h + 1) * 256 + 8 * lane;
    stcs4(rtop,     make_float4(o0[0], o1[0], o0[1], o1[1]));
    stcs4(rtop + 4, make_float4(o0[2], o1[2], o0[3], o1[3]));
    stcs4(rbot,     make_float4(o2[0], o3[0], o2[1], o3[1]));
    stcs4(rbot + 4, make_float4(o2[2], o3[2], o2[3], o3[3]));
}

__global__ __launch_bounds__(128, 8)
void inlwt_kernel(const float* __restrict__ in, float* __restrict__ out) {
    constexpr int H1 = 128, W1 = 128, C = 64;
    constexpr int HT = 8;                  // rows per warp strip
    // 16 h-tiles per (b,c) plane

    const int gw   = (blockIdx.x * blockDim.x + threadIdx.x) >> 5;  // 0..16383
    const int lane = threadIdx.x & 31;

    const int htile = gw & 15;
    const int cc    = (gw >> 4) & 63;
    const int b     = gw >> 10;

    const int h0 = htile * HT;
    const int w0 = lane * 4;

    const float* inb  = in  + (size_t)(b * 256 + cc) * (H1 * W1);
    float*       outb = out + (size_t)(b * C   + cc) * (size_t)(2 * H1) * (2 * W1);
    const size_t gs   = (size_t)64 * H1 * W1;   // channel-group stride

    // ---- prologue: halo row + first row, 8 loads issued back-to-back ----
    const int hp = (h0 == 0) ? (H1 - 1) : (h0 - 1);
    float4 pv0 = ldcs4(inb + 0 * gs + (size_t)hp * W1 + w0);
    float4 pv1 = ldcs4(inb + 1 * gs + (size_t)hp * W1 + w0);
    float4 pv2 = ldcs4(inb + 2 * gs + (size_t)hp * W1 + w0);
    float4 pv3 = ldcs4(inb + 3 * gs + (size_t)hp * W1 + w0);
    float4 cv0 = ldcs4(inb + 0 * gs + (size_t)h0 * W1 + w0);
    float4 cv1 = ldcs4(inb + 1 * gs + (size_t)h0 * W1 + w0);
    float4 cv2 = ldcs4(inb + 2 * gs + (size_t)h0 * W1 + w0);
    float4 cv3 = ldcs4(inb + 3 * gs + (size_t)h0 * W1 + w0);

    // ---- pipelined main loop: prefetch row h+1 before consuming row h ----
    #pragma unroll 7
    for (int h = h0; h < h0 + HT - 1; ++h) {
        const float* nrow = inb + (size_t)(h + 1) * W1 + w0;
        float4 nv0 = ldcs4(nrow + 0 * gs);
        float4 nv1 = ldcs4(nrow + 1 * gs);
        float4 nv2 = ldcs4(nrow + 2 * gs);
        float4 nv3 = ldcs4(nrow + 3 * gs);

        compute_store(pv0, pv1, pv2, pv3, cv0, cv1, cv2, cv3, outb, h, lane);

        pv0 = cv0; pv1 = cv1; pv2 = cv2; pv3 = cv3;
        cv0 = nv0; cv1 = nv1; cv2 = nv2; cv3 = nv3;
    }
    // epilogue: last row of the strip
    compute_store(pv0, pv1, pv2, pv3, cv0, cv1, cv2, cv3, outb, h0 + HT - 1, lane);
}

extern "C" void kernel_launch(void* const* d_in, const int* in_sizes, int n_in,
                              void* d_out, int out_size) {
    const float* in = (const float*)d_in[0];
    float* out = (float*)d_out;
    // 16 b * 64 c * 16 htiles = 16384 warps; 4 warps per block -> 4096 blocks.
    inlwt_kernel<<<4096, 128>>>(in, out);
}